// round 1
// baseline (speedup 1.0000x reference)
#include <cuda_runtime.h>
#include <cuda_fp16.h>
#include <cstdint>

#define NN 8192
#define TT 100

constexpr int TPB     = 256;          // threads per matvec block
constexpr int COLS_PB = 1024;         // columns per block (4 per thread)
constexpr int CCH     = NN / COLS_PB; // 8 column chunks
constexpr int ROWS_PB = 128;          // rows per block
constexpr int RCH     = NN / ROWS_PB; // 64 row chunks
constexpr int NBLK    = CCH * RCH;    // 512 blocks

// Scratch (device globals: no allocation allowed in kernel_launch)
__device__ __align__(16) __half g_tsh[(size_t)NN * NN];   // ts * N in fp16 (128 MB)
__device__ float    g_diag[NN];
__device__ float    g_state[3 * NN];                       // U | I | V (SoA)
__device__ float    g_k[4][3 * NN];
__device__ __align__(16) float g_partial[(size_t)RCH * NN];
__device__ unsigned g_cnt[CCH];

// ---------------------------------------------------------------------------
// Convert ts (fp32, [0,1/N)) -> fp16 scaled by N (exact power-of-2 scaling)
// ---------------------------------------------------------------------------
__global__ void convert_kernel(const float* __restrict__ ts) {
    size_t base = ((size_t)blockIdx.x * blockDim.x + threadIdx.x) * 8;
    float4 a = *reinterpret_cast<const float4*>(ts + base);
    float4 b = *reinterpret_cast<const float4*>(ts + base + 4);
    __half2 h0 = __floats2half2_rn(a.x * 8192.f, a.y * 8192.f);
    __half2 h1 = __floats2half2_rn(a.z * 8192.f, a.w * 8192.f);
    __half2 h2 = __floats2half2_rn(b.x * 8192.f, b.y * 8192.f);
    __half2 h3 = __floats2half2_rn(b.z * 8192.f, b.w * 8192.f);
    uint4 o;
    o.x = *reinterpret_cast<unsigned*>(&h0);
    o.y = *reinterpret_cast<unsigned*>(&h1);
    o.z = *reinterpret_cast<unsigned*>(&h2);
    o.w = *reinterpret_cast<unsigned*>(&h3);
    *reinterpret_cast<uint4*>(g_tsh + base) = o;
}

// ---------------------------------------------------------------------------
// Init: |x0| -> SoA state, diag (fp16-rounded for exact cancellation),
//       zero d_out and chunk counters.
// ---------------------------------------------------------------------------
__global__ void init_kernel(const float* __restrict__ x0,
                            const float* __restrict__ ts,
                            float* __restrict__ out) {
    int i = blockIdx.x * blockDim.x + threadIdx.x;
    if (i < NN) {
        g_state[i]          = fabsf(x0[3 * i + 0]);
        g_state[NN + i]     = fabsf(x0[3 * i + 1]);
        g_state[2 * NN + i] = fabsf(x0[3 * i + 2]);
        float d = ts[(size_t)i * NN + i] * 8192.f;
        g_diag[i] = __half2float(__float2half_rn(d)) * (1.f / 8192.f);
    }
    if (i < 3 * TT) out[i] = 0.f;
    if (i < CCH)    g_cnt[i] = 0u;
}

__device__ __forceinline__ float sigmoidf_(float z) {
    return 1.f / (1.f + expf(-z));
}

// t = 0 output row: sum over nodes of sigmoid(slope*(W@uiv + b - thr)) / N
__global__ void out0_kernel(const float* __restrict__ W, const float* __restrict__ bb,
                            const float* __restrict__ slope, const float* __restrict__ thr,
                            float* __restrict__ out) {
    int i = blockIdx.x * blockDim.x + threadIdx.x;
    float U = g_state[i], I = g_state[NN + i], V = g_state[2 * NN + i];
    float s[3];
#pragma unroll
    for (int m = 0; m < 3; ++m) {
        float lin = W[3 * m + 0] * U + W[3 * m + 1] * I + W[3 * m + 2] * V + bb[m];
        s[m] = sigmoidf_(slope[m] * (lin - thr[m]));
    }
#pragma unroll
    for (int o = 16; o > 0; o >>= 1) {
        s[0] += __shfl_down_sync(0xffffffffu, s[0], o);
        s[1] += __shfl_down_sync(0xffffffffu, s[1], o);
        s[2] += __shfl_down_sync(0xffffffffu, s[2], o);
    }
    __shared__ float red[3][8];
    int warp = threadIdx.x >> 5, lane = threadIdx.x & 31;
    if (lane == 0) { red[0][warp] = s[0]; red[1][warp] = s[1]; red[2][warp] = s[2]; }
    __syncthreads();
    if (threadIdx.x == 0) {
        float t0 = 0.f, t1 = 0.f, t2 = 0.f;
#pragma unroll
        for (int w = 0; w < 8; ++w) { t0 += red[0][w]; t1 += red[1][w]; t2 += red[2][w]; }
        atomicAdd(out + 0 * TT, t0 * (1.f / 8192.f));
        atomicAdd(out + 1 * TT, t1 * (1.f / 8192.f));
        atomicAdd(out + 2 * TT, t2 * (1.f / 8192.f));
    }
}

// ---------------------------------------------------------------------------
// One RK4 stage: split-K matvec coup = ts^T @ V_stage, last block per column
// chunk reduces partials (fixed order -> deterministic) and evaluates the RHS.
// Stage 4 additionally does the RK4 combine + output-row reduction.
// ---------------------------------------------------------------------------
template <int STAGE>
__global__ void __launch_bounds__(TPB) stage_kernel(
    const float* __restrict__ times, int step,
    const float* __restrict__ betas, const float* __restrict__ deltas,
    const float* __restrict__ cs, const float* __restrict__ ps,
    const float* __restrict__ W, const float* __restrict__ bb,
    const float* __restrict__ slope, const float* __restrict__ thr,
    float* __restrict__ out) {

    const float h  = times[step + 1] - times[step];
    const float ah = (STAGE == 1) ? 0.f : ((STAGE == 4) ? h : 0.5f * h);
    const float* kprev = g_k[(STAGE >= 2) ? (STAGE - 2) : 0];

    const int tid  = threadIdx.x;
    const int c    = blockIdx.x % CCH;
    const int r    = blockIdx.x / CCH;
    const int col0 = c * COLS_PB;
    const int row0 = r * ROWS_PB;

    __shared__ float sV[ROWS_PB];
    if (tid < ROWS_PB) {
        int j = row0 + tid;
        float v = g_state[2 * NN + j];
        if (STAGE > 1) v = fmaf(ah, kprev[2 * NN + j], v);
        sV[tid] = v;
    }
    __syncthreads();

    // Matvec partial: columns [col0 + 4*tid, +4), rows [row0, row0+128)
    float a0 = 0.f, a1 = 0.f, a2 = 0.f, a3 = 0.f;
    const uint2* mp = reinterpret_cast<const uint2*>(g_tsh + (size_t)row0 * NN + col0) + tid;
#pragma unroll 8
    for (int j = 0; j < ROWS_PB; ++j) {
        uint2 q = *mp;
        mp += NN / 4;
        float v = sV[j];
        __half2 p0 = *reinterpret_cast<__half2*>(&q.x);
        __half2 p1 = *reinterpret_cast<__half2*>(&q.y);
        float2 f0 = __half22float2(p0);
        float2 f1 = __half22float2(p1);
        a0 = fmaf(f0.x, v, a0);
        a1 = fmaf(f0.y, v, a1);
        a2 = fmaf(f1.x, v, a2);
        a3 = fmaf(f1.y, v, a3);
    }
    *reinterpret_cast<float4*>(g_partial + (size_t)r * NN + col0 + tid * 4) =
        make_float4(a0, a1, a2, a3);

    __threadfence();
    __syncthreads();
    __shared__ int s_last;
    if (tid == 0) {
        unsigned old = atomicAdd(&g_cnt[c], 1u);
        s_last = (old == RCH - 1);
    }
    __syncthreads();
    if (!s_last) return;
    if (tid == 0) g_cnt[c] = 0u;  // reset for next stage kernel

    // Deterministic ordered reduction over row chunks
    const int i0 = col0 + tid * 4;
    float c0 = 0.f, c1 = 0.f, c2 = 0.f, c3 = 0.f;
#pragma unroll 4
    for (int rr = 0; rr < RCH; ++rr) {
        float4 x = *reinterpret_cast<const float4*>(g_partial + (size_t)rr * NN + i0);
        c0 += x.x; c1 += x.y; c2 += x.z; c3 += x.w;
    }
    float coup[4] = {c0, c1, c2, c3};

    float s0 = 0.f, s1 = 0.f, s2 = 0.f;
    const float hd6 = h * (1.f / 6.f);

#pragma unroll
    for (int k = 0; k < 4; ++k) {
        int i = i0 + k;
        float U = g_state[i], I = g_state[NN + i], V = g_state[2 * NN + i];
        if (STAGE > 1) {
            U = fmaf(ah, kprev[i], U);
            I = fmaf(ah, kprev[NN + i], I);
            V = fmaf(ah, kprev[2 * NN + i], V);
        }
        float cp  = coup[k] * (1.f / 8192.f) - g_diag[i] * V;
        float inf = fabsf(betas[i]) * U * V;
        float kU  = -inf;
        float kI  = inf - fabsf(deltas[i]) * I;
        float kV  = fabsf(ps[i]) * I - fabsf(cs[i]) * V + cp;
        g_k[STAGE - 1][i]          = kU;
        g_k[STAGE - 1][NN + i]     = kI;
        g_k[STAGE - 1][2 * NN + i] = kV;

        if (STAGE == 4) {
            float nU = g_state[i]          + hd6 * (g_k[0][i]          + 2.f * g_k[1][i]          + 2.f * g_k[2][i]          + kU);
            float nI = g_state[NN + i]     + hd6 * (g_k[0][NN + i]     + 2.f * g_k[1][NN + i]     + 2.f * g_k[2][NN + i]     + kI);
            float nV = g_state[2 * NN + i] + hd6 * (g_k[0][2 * NN + i] + 2.f * g_k[1][2 * NN + i] + 2.f * g_k[2][2 * NN + i] + kV);
            g_state[i]          = nU;
            g_state[NN + i]     = nI;
            g_state[2 * NN + i] = nV;
#pragma unroll
            for (int m = 0; m < 3; ++m) {
                float lin = W[3 * m + 0] * nU + W[3 * m + 1] * nI + W[3 * m + 2] * nV + bb[m];
                float sg  = sigmoidf_(slope[m] * (lin - thr[m]));
                if (m == 0) s0 += sg; else if (m == 1) s1 += sg; else s2 += sg;
            }
        }
    }

    if (STAGE == 4) {
#pragma unroll
        for (int o = 16; o > 0; o >>= 1) {
            s0 += __shfl_down_sync(0xffffffffu, s0, o);
            s1 += __shfl_down_sync(0xffffffffu, s1, o);
            s2 += __shfl_down_sync(0xffffffffu, s2, o);
        }
        __shared__ float red[3][8];
        int warp = tid >> 5, lane = tid & 31;
        if (lane == 0) { red[0][warp] = s0; red[1][warp] = s1; red[2][warp] = s2; }
        __syncthreads();
        if (tid == 0) {
            float t0 = 0.f, t1 = 0.f, t2 = 0.f;
#pragma unroll
            for (int w = 0; w < 8; ++w) { t0 += red[0][w]; t1 += red[1][w]; t2 += red[2][w]; }
            atomicAdd(out + 0 * TT + step + 1, t0 * (1.f / 8192.f));
            atomicAdd(out + 1 * TT + step + 1, t1 * (1.f / 8192.f));
            atomicAdd(out + 2 * TT + step + 1, t2 * (1.f / 8192.f));
        }
    }
}

// ---------------------------------------------------------------------------
extern "C" void kernel_launch(void* const* d_in, const int* in_sizes, int n_in,
                              void* d_out, int out_size) {
    const float* times  = (const float*)d_in[0];
    const float* x0     = (const float*)d_in[1];
    const float* betas  = (const float*)d_in[2];
    const float* deltas = (const float*)d_in[3];
    const float* cs     = (const float*)d_in[4];
    const float* ps     = (const float*)d_in[5];
    const float* ts     = (const float*)d_in[6];
    const float* W      = (const float*)d_in[7];
    const float* b      = (const float*)d_in[8];
    const float* slope  = (const float*)d_in[9];
    const float* thr    = (const float*)d_in[10];
    float* out = (float*)d_out;

    // 64M elements, 8 per thread
    convert_kernel<<<(NN * (size_t)NN) / (256 * 8), 256>>>(ts);
    init_kernel<<<NN / 256, 256>>>(x0, ts, out);
    out0_kernel<<<NN / 256, 256>>>(W, b, slope, thr, out);

    for (int step = 0; step < TT - 1; ++step) {
        stage_kernel<1><<<NBLK, TPB>>>(times, step, betas, deltas, cs, ps, W, b, slope, thr, out);
        stage_kernel<2><<<NBLK, TPB>>>(times, step, betas, deltas, cs, ps, W, b, slope, thr, out);
        stage_kernel<3><<<NBLK, TPB>>>(times, step, betas, deltas, cs, ps, W, b, slope, thr, out);
        stage_kernel<4><<<NBLK, TPB>>>(times, step, betas, deltas, cs, ps, W, b, slope, thr, out);
    }
}

// round 2
// speedup vs baseline: 1.2786x; 1.2786x over previous
#include <cuda_runtime.h>
#include <cuda_fp16.h>
#include <cuda_fp8.h>
#include <cstdint>

#define NN 8192
#define TT 100

constexpr int TPB     = 256;           // threads per matvec block
constexpr int COLS_PB = 1024;          // columns per block (16/thread, 64 threads/row-group)
constexpr int CCH     = NN / COLS_PB;  // 8 column chunks
constexpr int ROWS_PB = 64;            // rows per block
constexpr int RCH     = NN / ROWS_PB;  // 128 row chunks
constexpr int NBLK    = CCH * RCH;     // 1024 blocks

// Scratch (device globals: no allocation allowed in kernel_launch)
__device__ __align__(16) unsigned char g_ts8[(size_t)NN * NN]; // ts * N in e4m3 (64 MB)
__device__ float    g_diag[NN];
__device__ float    g_state[3 * NN];                            // U | I | V (SoA)
__device__ float    g_k[4][3 * NN];
__device__ __align__(16) float g_partial[(size_t)RCH * NN];     // 4 MB
__device__ unsigned g_cnt[CCH];

// ---------------------------------------------------------------------------
// Convert ts (fp32, [0,1/N)) -> e4m3 scaled by N (exact power-of-2 scaling)
// ---------------------------------------------------------------------------
__global__ void convert_kernel(const float* __restrict__ ts) {
    size_t base = ((size_t)blockIdx.x * blockDim.x + threadIdx.x) * 16;
    unsigned w[4];
#pragma unroll
    for (int u = 0; u < 4; ++u) {
        float4 f = *reinterpret_cast<const float4*>(ts + base + u * 4);
        __nv_fp8x2_storage_t lo = __nv_cvt_float2_to_fp8x2(
            make_float2(f.x * 8192.f, f.y * 8192.f), __NV_SATFINITE, __NV_E4M3);
        __nv_fp8x2_storage_t hi = __nv_cvt_float2_to_fp8x2(
            make_float2(f.z * 8192.f, f.w * 8192.f), __NV_SATFINITE, __NV_E4M3);
        w[u] = (unsigned)lo | ((unsigned)hi << 16);
    }
    *reinterpret_cast<uint4*>(g_ts8 + base) = make_uint4(w[0], w[1], w[2], w[3]);
}

// ---------------------------------------------------------------------------
// Init: |x0| -> SoA state, diag (e4m3-rounded for exact cancellation),
//       zero d_out and chunk counters.
// ---------------------------------------------------------------------------
__global__ void init_kernel(const float* __restrict__ x0,
                            const float* __restrict__ ts,
                            float* __restrict__ out) {
    int i = blockIdx.x * blockDim.x + threadIdx.x;
    if (i < NN) {
        g_state[i]          = fabsf(x0[3 * i + 0]);
        g_state[NN + i]     = fabsf(x0[3 * i + 1]);
        g_state[2 * NN + i] = fabsf(x0[3 * i + 2]);
        float d = ts[(size_t)i * NN + i] * 8192.f;
        __nv_fp8_storage_t s8 = __nv_cvt_float_to_fp8(d, __NV_SATFINITE, __NV_E4M3);
        __half_raw hr = __nv_cvt_fp8_to_halfraw(s8, __NV_E4M3);
        g_diag[i] = __half2float(__half(hr)) * (1.f / 8192.f);
    }
    if (i < 3 * TT) out[i] = 0.f;
    if (i < CCH)    g_cnt[i] = 0u;
}

__device__ __forceinline__ float sigmoidf_(float z) {
    return 1.f / (1.f + expf(-z));
}

// t = 0 output row
__global__ void out0_kernel(const float* __restrict__ W, const float* __restrict__ bb,
                            const float* __restrict__ slope, const float* __restrict__ thr,
                            float* __restrict__ out) {
    int i = blockIdx.x * blockDim.x + threadIdx.x;
    float U = g_state[i], I = g_state[NN + i], V = g_state[2 * NN + i];
    float s[3];
#pragma unroll
    for (int m = 0; m < 3; ++m) {
        float lin = W[3 * m + 0] * U + W[3 * m + 1] * I + W[3 * m + 2] * V + bb[m];
        s[m] = sigmoidf_(slope[m] * (lin - thr[m]));
    }
#pragma unroll
    for (int o = 16; o > 0; o >>= 1) {
        s[0] += __shfl_down_sync(0xffffffffu, s[0], o);
        s[1] += __shfl_down_sync(0xffffffffu, s[1], o);
        s[2] += __shfl_down_sync(0xffffffffu, s[2], o);
    }
    __shared__ float red[3][8];
    int warp = threadIdx.x >> 5, lane = threadIdx.x & 31;
    if (lane == 0) { red[0][warp] = s[0]; red[1][warp] = s[1]; red[2][warp] = s[2]; }
    __syncthreads();
    if (threadIdx.x == 0) {
        float t0 = 0.f, t1 = 0.f, t2 = 0.f;
#pragma unroll
        for (int w = 0; w < 8; ++w) { t0 += red[0][w]; t1 += red[1][w]; t2 += red[2][w]; }
        atomicAdd(out + 0 * TT, t0 * (1.f / 8192.f));
        atomicAdd(out + 1 * TT, t1 * (1.f / 8192.f));
        atomicAdd(out + 2 * TT, t2 * (1.f / 8192.f));
    }
}

// 4 e4m3 values in a uint32 -> fma into a[0..3]
__device__ __forceinline__ void acc4(unsigned w, float v, float* a) {
    __half2 h0 = __half2(__nv_cvt_fp8x2_to_halfraw2((__nv_fp8x2_storage_t)(w & 0xffffu), __NV_E4M3));
    __half2 h1 = __half2(__nv_cvt_fp8x2_to_halfraw2((__nv_fp8x2_storage_t)(w >> 16), __NV_E4M3));
    float2 f0 = __half22float2(h0);
    float2 f1 = __half22float2(h1);
    a[0] = fmaf(f0.x, v, a[0]);
    a[1] = fmaf(f0.y, v, a[1]);
    a[2] = fmaf(f1.x, v, a[2]);
    a[3] = fmaf(f1.y, v, a[3]);
}

// ---------------------------------------------------------------------------
// One RK4 stage: split-K matvec coup = ts^T @ V_stage; last block per column
// chunk reduces partials in fixed order (deterministic) and evaluates the RHS.
// Stage 4 additionally does the RK4 combine + output-row reduction.
// ---------------------------------------------------------------------------
template <int STAGE>
__global__ void __launch_bounds__(TPB) stage_kernel(
    const float* __restrict__ times, int step,
    const float* __restrict__ betas, const float* __restrict__ deltas,
    const float* __restrict__ cs, const float* __restrict__ ps,
    const float* __restrict__ W, const float* __restrict__ bb,
    const float* __restrict__ slope, const float* __restrict__ thr,
    float* __restrict__ out) {

    const float h  = times[step + 1] - times[step];
    const float ah = (STAGE == 1) ? 0.f : ((STAGE == 4) ? h : 0.5f * h);
    const float* kprev = g_k[(STAGE >= 2) ? (STAGE - 2) : 0];

    const int tid  = threadIdx.x;
    const int c    = blockIdx.x & (CCH - 1);
    const int r    = blockIdx.x / CCH;
    const int col0 = c * COLS_PB;
    const int row0 = r * ROWS_PB;
    const int tsub = tid & 63;       // 64 threads span 1024 cols (16 each)
    const int rg   = tid >> 6;       // 4 row groups
    const int cbase = col0 + tsub * 16;

    __shared__ float sV[ROWS_PB];
    __shared__ float sred[16 * 128]; // [k][grp*64 + tsub], conflict-free

    if (tid < ROWS_PB) {
        int j = row0 + tid;
        float v = g_state[2 * NN + j];
        if (STAGE > 1) v = fmaf(ah, kprev[2 * NN + j], v);
        sV[tid] = v;
    }
    __syncthreads();

    float acc[16];
#pragma unroll
    for (int k = 0; k < 16; ++k) acc[k] = 0.f;

    const uint4* mp = reinterpret_cast<const uint4*>(g_ts8 + (size_t)(row0 + rg) * NN + cbase);
#pragma unroll 4
    for (int i = rg; i < ROWS_PB; i += 4) {
        uint4 q = *mp;
        mp += (4 * NN) / 16;
        float v = sV[i];
        acc4(q.x, v, acc);
        acc4(q.y, v, acc + 4);
        acc4(q.z, v, acc + 8);
        acc4(q.w, v, acc + 12);
    }

    // Cross row-group reduction in shared memory (fixed order: (0+2) + (1+3))
    if (rg >= 2) {
#pragma unroll
        for (int k = 0; k < 16; ++k) sred[k * 128 + (rg - 2) * 64 + tsub] = acc[k];
    }
    __syncthreads();
    if (rg < 2) {
#pragma unroll
        for (int k = 0; k < 16; ++k) acc[k] += sred[k * 128 + rg * 64 + tsub];
    }
    __syncthreads();
    if (rg == 1) {
#pragma unroll
        for (int k = 0; k < 16; ++k) sred[k * 128 + tsub] = acc[k];
    }
    __syncthreads();
    if (rg == 0) {
#pragma unroll
        for (int k = 0; k < 16; ++k) acc[k] += sred[k * 128 + tsub];
        float4* pp = reinterpret_cast<float4*>(g_partial + (size_t)r * NN + cbase);
        pp[0] = make_float4(acc[0],  acc[1],  acc[2],  acc[3]);
        pp[1] = make_float4(acc[4],  acc[5],  acc[6],  acc[7]);
        pp[2] = make_float4(acc[8],  acc[9],  acc[10], acc[11]);
        pp[3] = make_float4(acc[12], acc[13], acc[14], acc[15]);
    }

    __threadfence();
    __syncthreads();
    __shared__ int s_last;
    if (tid == 0) {
        unsigned old = atomicAdd(&g_cnt[c], 1u);
        s_last = (old == RCH - 1);
    }
    __syncthreads();
    if (!s_last) return;
    if (tid == 0) g_cnt[c] = 0u;  // reset for next stage kernel

    // Deterministic ordered reduction over row chunks (4 cols per thread)
    const int i0 = col0 + tid * 4;
    float c0 = 0.f, c1 = 0.f, c2 = 0.f, c3 = 0.f;
#pragma unroll 8
    for (int rr = 0; rr < RCH; ++rr) {
        float4 x = *reinterpret_cast<const float4*>(g_partial + (size_t)rr * NN + i0);
        c0 += x.x; c1 += x.y; c2 += x.z; c3 += x.w;
    }
    float coup[4] = {c0, c1, c2, c3};

    float s0 = 0.f, s1 = 0.f, s2 = 0.f;
    const float hd6 = h * (1.f / 6.f);

#pragma unroll
    for (int k = 0; k < 4; ++k) {
        int i = i0 + k;
        float U = g_state[i], I = g_state[NN + i], V = g_state[2 * NN + i];
        if (STAGE > 1) {
            U = fmaf(ah, kprev[i], U);
            I = fmaf(ah, kprev[NN + i], I);
            V = fmaf(ah, kprev[2 * NN + i], V);
        }
        float cp  = coup[k] * (1.f / 8192.f) - g_diag[i] * V;
        float inf = fabsf(betas[i]) * U * V;
        float kU  = -inf;
        float kI  = inf - fabsf(deltas[i]) * I;
        float kV  = fabsf(ps[i]) * I - fabsf(cs[i]) * V + cp;
        g_k[STAGE - 1][i]          = kU;
        g_k[STAGE - 1][NN + i]     = kI;
        g_k[STAGE - 1][2 * NN + i] = kV;

        if (STAGE == 4) {
            float nU = g_state[i]          + hd6 * (g_k[0][i]          + 2.f * g_k[1][i]          + 2.f * g_k[2][i]          + kU);
            float nI = g_state[NN + i]     + hd6 * (g_k[0][NN + i]     + 2.f * g_k[1][NN + i]     + 2.f * g_k[2][NN + i]     + kI);
            float nV = g_state[2 * NN + i] + hd6 * (g_k[0][2 * NN + i] + 2.f * g_k[1][2 * NN + i] + 2.f * g_k[2][2 * NN + i] + kV);
            g_state[i]          = nU;
            g_state[NN + i]     = nI;
            g_state[2 * NN + i] = nV;
#pragma unroll
            for (int m = 0; m < 3; ++m) {
                float lin = W[3 * m + 0] * nU + W[3 * m + 1] * nI + W[3 * m + 2] * nV + bb[m];
                float sg  = sigmoidf_(slope[m] * (lin - thr[m]));
                if (m == 0) s0 += sg; else if (m == 1) s1 += sg; else s2 += sg;
            }
        }
    }

    if (STAGE == 4) {
#pragma unroll
        for (int o = 16; o > 0; o >>= 1) {
            s0 += __shfl_down_sync(0xffffffffu, s0, o);
            s1 += __shfl_down_sync(0xffffffffu, s1, o);
            s2 += __shfl_down_sync(0xffffffffu, s2, o);
        }
        __shared__ float red[3][8];
        int warp = tid >> 5, lane = tid & 31;
        if (lane == 0) { red[0][warp] = s0; red[1][warp] = s1; red[2][warp] = s2; }
        __syncthreads();
        if (tid == 0) {
            float t0 = 0.f, t1 = 0.f, t2 = 0.f;
#pragma unroll
            for (int w = 0; w < 8; ++w) { t0 += red[0][w]; t1 += red[1][w]; t2 += red[2][w]; }
            atomicAdd(out + 0 * TT + step + 1, t0 * (1.f / 8192.f));
            atomicAdd(out + 1 * TT + step + 1, t1 * (1.f / 8192.f));
            atomicAdd(out + 2 * TT + step + 1, t2 * (1.f / 8192.f));
        }
    }
}

// ---------------------------------------------------------------------------
extern "C" void kernel_launch(void* const* d_in, const int* in_sizes, int n_in,
                              void* d_out, int out_size) {
    const float* times  = (const float*)d_in[0];
    const float* x0     = (const float*)d_in[1];
    const float* betas  = (const float*)d_in[2];
    const float* deltas = (const float*)d_in[3];
    const float* cs     = (const float*)d_in[4];
    const float* ps     = (const float*)d_in[5];
    const float* ts     = (const float*)d_in[6];
    const float* W      = (const float*)d_in[7];
    const float* b      = (const float*)d_in[8];
    const float* slope  = (const float*)d_in[9];
    const float* thr    = (const float*)d_in[10];
    float* out = (float*)d_out;

    // 64M elements, 16 per thread
    convert_kernel<<<(int)(((size_t)NN * NN) / (256 * 16)), 256>>>(ts);
    init_kernel<<<NN / 256, 256>>>(x0, ts, out);
    out0_kernel<<<NN / 256, 256>>>(W, b, slope, thr, out);

    for (int step = 0; step < TT - 1; ++step) {
        stage_kernel<1><<<NBLK, TPB>>>(times, step, betas, deltas, cs, ps, W, b, slope, thr, out);
        stage_kernel<2><<<NBLK, TPB>>>(times, step, betas, deltas, cs, ps, W, b, slope, thr, out);
        stage_kernel<3><<<NBLK, TPB>>>(times, step, betas, deltas, cs, ps, W, b, slope, thr, out);
        stage_kernel<4><<<NBLK, TPB>>>(times, step, betas, deltas, cs, ps, W, b, slope, thr, out);
    }
}

// round 3
// speedup vs baseline: 1.6631x; 1.3007x over previous
#include <cuda_runtime.h>
#include <cuda_fp16.h>
#include <cuda_fp8.h>
#include <cstdint>

#define NN 8192
#define TT 100

constexpr int TPB     = 256;           // threads per matvec block
constexpr int COLS_PB = 1024;          // columns per block (16/thread, 64 threads/row-group)
constexpr int CCH     = NN / COLS_PB;  // 8 column chunks
constexpr int ROWS_PB = 64;            // rows per block
constexpr int RCH     = NN / ROWS_PB;  // 128 row chunks
constexpr int NBLK    = CCH * RCH;     // 1024 blocks

// Scratch (device globals: no allocation allowed in kernel_launch)
__device__ __align__(16) unsigned char g_ts8[(size_t)NN * NN]; // ts * N in e4m3 (64 MB)
__device__ float    g_diag[NN];
__device__ float    g_state[3 * NN];                            // U | I | V (SoA)
__device__ float    g_k[4][3 * NN];
__device__ __align__(16) float g_partial[(size_t)RCH * NN];     // 4 MB
__device__ unsigned g_cnt[CCH];

// ---------------------------------------------------------------------------
// Convert ts (fp32, [0,1/N)) -> e4m3 scaled by N (exact power-of-2 scaling)
// ---------------------------------------------------------------------------
__global__ void convert_kernel(const float* __restrict__ ts) {
    size_t base = ((size_t)blockIdx.x * blockDim.x + threadIdx.x) * 16;
    unsigned w[4];
#pragma unroll
    for (int u = 0; u < 4; ++u) {
        float4 f = *reinterpret_cast<const float4*>(ts + base + u * 4);
        __nv_fp8x2_storage_t lo = __nv_cvt_float2_to_fp8x2(
            make_float2(f.x * 8192.f, f.y * 8192.f), __NV_SATFINITE, __NV_E4M3);
        __nv_fp8x2_storage_t hi = __nv_cvt_float2_to_fp8x2(
            make_float2(f.z * 8192.f, f.w * 8192.f), __NV_SATFINITE, __NV_E4M3);
        w[u] = (unsigned)lo | ((unsigned)hi << 16);
    }
    *reinterpret_cast<uint4*>(g_ts8 + base) = make_uint4(w[0], w[1], w[2], w[3]);
}

// ---------------------------------------------------------------------------
// Init: |x0| -> SoA state, diag (e4m3-rounded for cancellation),
//       zero d_out and chunk counters.
// ---------------------------------------------------------------------------
__global__ void init_kernel(const float* __restrict__ x0,
                            const float* __restrict__ ts,
                            float* __restrict__ out) {
    int i = blockIdx.x * blockDim.x + threadIdx.x;
    if (i < NN) {
        g_state[i]          = fabsf(x0[3 * i + 0]);
        g_state[NN + i]     = fabsf(x0[3 * i + 1]);
        g_state[2 * NN + i] = fabsf(x0[3 * i + 2]);
        float d = ts[(size_t)i * NN + i] * 8192.f;
        __nv_fp8_storage_t s8 = __nv_cvt_float_to_fp8(d, __NV_SATFINITE, __NV_E4M3);
        __half_raw hr = __nv_cvt_fp8_to_halfraw(s8, __NV_E4M3);
        g_diag[i] = __half2float(__half(hr)) * (1.f / 8192.f);
    }
    if (i < 3 * TT) out[i] = 0.f;
    if (i < CCH)    g_cnt[i] = 0u;
}

__device__ __forceinline__ float sigmoidf_(float z) {
    return 1.f / (1.f + expf(-z));
}

// t = 0 output row
__global__ void out0_kernel(const float* __restrict__ W, const float* __restrict__ bb,
                            const float* __restrict__ slope, const float* __restrict__ thr,
                            float* __restrict__ out) {
    int i = blockIdx.x * blockDim.x + threadIdx.x;
    float U = g_state[i], I = g_state[NN + i], V = g_state[2 * NN + i];
    float s[3];
#pragma unroll
    for (int m = 0; m < 3; ++m) {
        float lin = W[3 * m + 0] * U + W[3 * m + 1] * I + W[3 * m + 2] * V + bb[m];
        s[m] = sigmoidf_(slope[m] * (lin - thr[m]));
    }
#pragma unroll
    for (int o = 16; o > 0; o >>= 1) {
        s[0] += __shfl_down_sync(0xffffffffu, s[0], o);
        s[1] += __shfl_down_sync(0xffffffffu, s[1], o);
        s[2] += __shfl_down_sync(0xffffffffu, s[2], o);
    }
    __shared__ float red[3][8];
    int warp = threadIdx.x >> 5, lane = threadIdx.x & 31;
    if (lane == 0) { red[0][warp] = s[0]; red[1][warp] = s[1]; red[2][warp] = s[2]; }
    __syncthreads();
    if (threadIdx.x == 0) {
        float t0 = 0.f, t1 = 0.f, t2 = 0.f;
#pragma unroll
        for (int w = 0; w < 8; ++w) { t0 += red[0][w]; t1 += red[1][w]; t2 += red[2][w]; }
        atomicAdd(out + 0 * TT, t0 * (1.f / 8192.f));
        atomicAdd(out + 1 * TT, t1 * (1.f / 8192.f));
        atomicAdd(out + 2 * TT, t2 * (1.f / 8192.f));
    }
}

// 4 e4m3 values in a u32 -> 2 cvt + 2 HFMA2 into half2 accumulators
__device__ __forceinline__ void acch(unsigned w, __half2 vv, __half2& a0, __half2& a1) {
    __half2 h0 = __half2(__nv_cvt_fp8x2_to_halfraw2((__nv_fp8x2_storage_t)(w & 0xffffu), __NV_E4M3));
    __half2 h1 = __half2(__nv_cvt_fp8x2_to_halfraw2((__nv_fp8x2_storage_t)(w >> 16), __NV_E4M3));
    a0 = __hfma2(h0, vv, a0);
    a1 = __hfma2(h1, vv, a1);
}

// ---------------------------------------------------------------------------
// One RK4 stage: split-K matvec coup = ts^T @ V_stage; last block per column
// chunk reduces partials in fixed order (deterministic) and evaluates the RHS.
// Stage 4 additionally does the RK4 combine + output-row reduction.
// ---------------------------------------------------------------------------
template <int STAGE>
__global__ void __launch_bounds__(TPB) stage_kernel(
    const float* __restrict__ times, int step,
    const float* __restrict__ betas, const float* __restrict__ deltas,
    const float* __restrict__ cs, const float* __restrict__ ps,
    const float* __restrict__ W, const float* __restrict__ bb,
    const float* __restrict__ slope, const float* __restrict__ thr,
    float* __restrict__ out) {

    const float h  = times[step + 1] - times[step];
    const float ah = (STAGE == 1) ? 0.f : ((STAGE == 4) ? h : 0.5f * h);
    const float* kprev = g_k[(STAGE >= 2) ? (STAGE - 2) : 0];

    const int tid  = threadIdx.x;
    const int c    = blockIdx.x & (CCH - 1);
    const int r    = blockIdx.x / CCH;
    const int col0 = c * COLS_PB;
    const int row0 = r * ROWS_PB;
    const int tsub = tid & 63;       // 64 threads span 1024 cols (16 each)
    const int rg   = tid >> 6;       // 4 row groups
    const int cbase = col0 + tsub * 16;

    __shared__ __half2 sV2[ROWS_PB];
    __shared__ float sred[16 * 128]; // [k][grp*64 + tsub]

    if (tid < ROWS_PB) {
        int j = row0 + tid;
        float v = g_state[2 * NN + j];
        if (STAGE > 1) v = fmaf(ah, kprev[2 * NN + j], v);
        sV2[tid] = __float2half2_rn(v);
    }
    __syncthreads();

    // half2 accumulators: hacc[k] holds cols (cbase+2k, cbase+2k+1); 16 adds each.
    __half2 hacc[8];
#pragma unroll
    for (int k = 0; k < 8; ++k) hacc[k] = __float2half2_rn(0.f);

    constexpr size_t RSTRIDE = (size_t)(4 * NN) / 16;   // uint4 elems per 4 rows
    const uint4* mp = reinterpret_cast<const uint4*>(g_ts8 + (size_t)(row0 + rg) * NN + cbase);
    uint4 q = *mp;
#pragma unroll
    for (int it = 0; it < ROWS_PB / 4; ++it) {
        uint4 cur = q;
        if (it < ROWS_PB / 4 - 1) q = mp[RSTRIDE * (it + 1)];   // prefetch next row
        __half2 vv = sV2[rg + it * 4];
        acch(cur.x, vv, hacc[0], hacc[1]);
        acch(cur.y, vv, hacc[2], hacc[3]);
        acch(cur.z, vv, hacc[4], hacc[5]);
        acch(cur.w, vv, hacc[6], hacc[7]);
    }

    float acc[16];
#pragma unroll
    for (int k = 0; k < 8; ++k) {
        float2 f = __half22float2(hacc[k]);
        acc[2 * k]     = f.x;
        acc[2 * k + 1] = f.y;
    }

    // Cross row-group reduction in shared memory (fixed order: (0+2) + (1+3))
    if (rg >= 2) {
#pragma unroll
        for (int k = 0; k < 16; ++k) sred[k * 128 + (rg - 2) * 64 + tsub] = acc[k];
    }
    __syncthreads();
    if (rg < 2) {
#pragma unroll
        for (int k = 0; k < 16; ++k) acc[k] += sred[k * 128 + rg * 64 + tsub];
    }
    __syncthreads();
    if (rg == 1) {
#pragma unroll
        for (int k = 0; k < 16; ++k) sred[k * 128 + tsub] = acc[k];
    }
    __syncthreads();
    if (rg == 0) {
#pragma unroll
        for (int k = 0; k < 16; ++k) acc[k] += sred[k * 128 + tsub];
        float4* pp = reinterpret_cast<float4*>(g_partial + (size_t)r * NN + cbase);
        pp[0] = make_float4(acc[0],  acc[1],  acc[2],  acc[3]);
        pp[1] = make_float4(acc[4],  acc[5],  acc[6],  acc[7]);
        pp[2] = make_float4(acc[8],  acc[9],  acc[10], acc[11]);
        pp[3] = make_float4(acc[12], acc[13], acc[14], acc[15]);
    }

    __threadfence();
    __syncthreads();
    __shared__ int s_last;
    if (tid == 0) {
        unsigned old = atomicAdd(&g_cnt[c], 1u);
        s_last = (old == RCH - 1);
    }
    __syncthreads();
    if (!s_last) return;
    if (tid == 0) g_cnt[c] = 0u;  // reset for next stage kernel

    // Deterministic ordered reduction over row chunks (4 cols per thread)
    const int i0 = col0 + tid * 4;
    float c0 = 0.f, c1 = 0.f, c2 = 0.f, c3 = 0.f;
#pragma unroll 16
    for (int rr = 0; rr < RCH; ++rr) {
        float4 x = *reinterpret_cast<const float4*>(g_partial + (size_t)rr * NN + i0);
        c0 += x.x; c1 += x.y; c2 += x.z; c3 += x.w;
    }
    float coup[4] = {c0, c1, c2, c3};

    float s0 = 0.f, s1 = 0.f, s2 = 0.f;
    const float hd6 = h * (1.f / 6.f);

#pragma unroll
    for (int k = 0; k < 4; ++k) {
        int i = i0 + k;
        float U = g_state[i], I = g_state[NN + i], V = g_state[2 * NN + i];
        if (STAGE > 1) {
            U = fmaf(ah, kprev[i], U);
            I = fmaf(ah, kprev[NN + i], I);
            V = fmaf(ah, kprev[2 * NN + i], V);
        }
        float cp  = coup[k] * (1.f / 8192.f) - g_diag[i] * V;
        float inf = fabsf(betas[i]) * U * V;
        float kU  = -inf;
        float kI  = inf - fabsf(deltas[i]) * I;
        float kV  = fabsf(ps[i]) * I - fabsf(cs[i]) * V + cp;
        g_k[STAGE - 1][i]          = kU;
        g_k[STAGE - 1][NN + i]     = kI;
        g_k[STAGE - 1][2 * NN + i] = kV;

        if (STAGE == 4) {
            float nU = g_state[i]          + hd6 * (g_k[0][i]          + 2.f * g_k[1][i]          + 2.f * g_k[2][i]          + kU);
            float nI = g_state[NN + i]     + hd6 * (g_k[0][NN + i]     + 2.f * g_k[1][NN + i]     + 2.f * g_k[2][NN + i]     + kI);
            float nV = g_state[2 * NN + i] + hd6 * (g_k[0][2 * NN + i] + 2.f * g_k[1][2 * NN + i] + 2.f * g_k[2][2 * NN + i] + kV);
            g_state[i]          = nU;
            g_state[NN + i]     = nI;
            g_state[2 * NN + i] = nV;
#pragma unroll
            for (int m = 0; m < 3; ++m) {
                float lin = W[3 * m + 0] * nU + W[3 * m + 1] * nI + W[3 * m + 2] * nV + bb[m];
                float sg  = sigmoidf_(slope[m] * (lin - thr[m]));
                if (m == 0) s0 += sg; else if (m == 1) s1 += sg; else s2 += sg;
            }
        }
    }

    if (STAGE == 4) {
#pragma unroll
        for (int o = 16; o > 0; o >>= 1) {
            s0 += __shfl_down_sync(0xffffffffu, s0, o);
            s1 += __shfl_down_sync(0xffffffffu, s1, o);
            s2 += __shfl_down_sync(0xffffffffu, s2, o);
        }
        __shared__ float red[3][8];
        int warp = tid >> 5, lane = tid & 31;
        if (lane == 0) { red[0][warp] = s0; red[1][warp] = s1; red[2][warp] = s2; }
        __syncthreads();
        if (tid == 0) {
            float t0 = 0.f, t1 = 0.f, t2 = 0.f;
#pragma unroll
            for (int w = 0; w < 8; ++w) { t0 += red[0][w]; t1 += red[1][w]; t2 += red[2][w]; }
            atomicAdd(out + 0 * TT + step + 1, t0 * (1.f / 8192.f));
            atomicAdd(out + 1 * TT + step + 1, t1 * (1.f / 8192.f));
            atomicAdd(out + 2 * TT + step + 1, t2 * (1.f / 8192.f));
        }
    }
}

// ---------------------------------------------------------------------------
extern "C" void kernel_launch(void* const* d_in, const int* in_sizes, int n_in,
                              void* d_out, int out_size) {
    const float* times  = (const float*)d_in[0];
    const float* x0     = (const float*)d_in[1];
    const float* betas  = (const float*)d_in[2];
    const float* deltas = (const float*)d_in[3];
    const float* cs     = (const float*)d_in[4];
    const float* ps     = (const float*)d_in[5];
    const float* ts     = (const float*)d_in[6];
    const float* W      = (const float*)d_in[7];
    const float* b      = (const float*)d_in[8];
    const float* slope  = (const float*)d_in[9];
    const float* thr    = (const float*)d_in[10];
    float* out = (float*)d_out;

    convert_kernel<<<(int)(((size_t)NN * NN) / (256 * 16)), 256>>>(ts);
    init_kernel<<<NN / 256, 256>>>(x0, ts, out);
    out0_kernel<<<NN / 256, 256>>>(W, b, slope, thr, out);

    for (int step = 0; step < TT - 1; ++step) {
        stage_kernel<1><<<NBLK, TPB>>>(times, step, betas, deltas, cs, ps, W, b, slope, thr, out);
        stage_kernel<2><<<NBLK, TPB>>>(times, step, betas, deltas, cs, ps, W, b, slope, thr, out);
        stage_kernel<3><<<NBLK, TPB>>>(times, step, betas, deltas, cs, ps, W, b, slope, thr, out);
        stage_kernel<4><<<NBLK, TPB>>>(times, step, betas, deltas, cs, ps, W, b, slope, thr, out);
    }
}

// round 4
// speedup vs baseline: 2.2189x; 1.3342x over previous
#include <cuda_runtime.h>
#include <cuda_fp16.h>
#include <cuda_fp8.h>
#include <cstdint>

#define NN 8192
#define TT 100

constexpr int TPB     = 256;           // threads per block
constexpr int COLS_PB = 1024;          // columns per block (16/thread over 64 threads)
constexpr int CCH     = NN / COLS_PB;  // 8 column chunks
constexpr int ROWS_PB = 128;           // rows per block
constexpr int RCH     = NN / ROWS_PB;  // 64 row chunks
constexpr int NBLK    = CCH * RCH;     // 512 blocks (co-resident: 4/SM * 148 = 592)

// Scratch (device globals: no allocation allowed in kernel_launch)
__device__ __align__(16) unsigned char g_ts8[(size_t)NN * NN]; // ts * N in e4m3 (64 MB)
__device__ float    g_diag[NN];
__device__ float    g_state[3 * NN];                            // U | I | V (SoA)
__device__ float    g_k[4][3 * NN];
__device__ __align__(16) float g_partial[(size_t)RCH * NN];     // 2 MB
__device__ unsigned g_cnt[CCH];
__device__ unsigned g_arrive;
__device__ unsigned g_gen;

// ---------------------------------------------------------------------------
__global__ void convert_kernel(const float* __restrict__ ts) {
    size_t base = ((size_t)blockIdx.x * blockDim.x + threadIdx.x) * 16;
    unsigned w[4];
#pragma unroll
    for (int u = 0; u < 4; ++u) {
        float4 f = *reinterpret_cast<const float4*>(ts + base + u * 4);
        __nv_fp8x2_storage_t lo = __nv_cvt_float2_to_fp8x2(
            make_float2(f.x * 8192.f, f.y * 8192.f), __NV_SATFINITE, __NV_E4M3);
        __nv_fp8x2_storage_t hi = __nv_cvt_float2_to_fp8x2(
            make_float2(f.z * 8192.f, f.w * 8192.f), __NV_SATFINITE, __NV_E4M3);
        w[u] = (unsigned)lo | ((unsigned)hi << 16);
    }
    *reinterpret_cast<uint4*>(g_ts8 + base) = make_uint4(w[0], w[1], w[2], w[3]);
}

__global__ void init_kernel(const float* __restrict__ x0,
                            const float* __restrict__ ts,
                            float* __restrict__ out) {
    int i = blockIdx.x * blockDim.x + threadIdx.x;
    if (i < NN) {
        g_state[i]          = fabsf(x0[3 * i + 0]);
        g_state[NN + i]     = fabsf(x0[3 * i + 1]);
        g_state[2 * NN + i] = fabsf(x0[3 * i + 2]);
        float d = ts[(size_t)i * NN + i] * 8192.f;
        __nv_fp8_storage_t s8 = __nv_cvt_float_to_fp8(d, __NV_SATFINITE, __NV_E4M3);
        __half_raw hr = __nv_cvt_fp8_to_halfraw(s8, __NV_E4M3);
        g_diag[i] = __half2float(__half(hr)) * (1.f / 8192.f);
    }
    if (i < 3 * TT) out[i] = 0.f;
    if (i < CCH)    g_cnt[i] = 0u;
    if (i == 0)     { g_arrive = 0u; g_gen = 0u; }   // reset per replay (graph-safe)
}

__device__ __forceinline__ float sigmoidf_(float z) {
    return 1.f / (1.f + expf(-z));
}

__global__ void out0_kernel(const float* __restrict__ W, const float* __restrict__ bb,
                            const float* __restrict__ slope, const float* __restrict__ thr,
                            float* __restrict__ out) {
    int i = blockIdx.x * blockDim.x + threadIdx.x;
    float U = g_state[i], I = g_state[NN + i], V = g_state[2 * NN + i];
    float s[3];
#pragma unroll
    for (int m = 0; m < 3; ++m) {
        float lin = W[3 * m + 0] * U + W[3 * m + 1] * I + W[3 * m + 2] * V + bb[m];
        s[m] = sigmoidf_(slope[m] * (lin - thr[m]));
    }
#pragma unroll
    for (int o = 16; o > 0; o >>= 1) {
        s[0] += __shfl_down_sync(0xffffffffu, s[0], o);
        s[1] += __shfl_down_sync(0xffffffffu, s[1], o);
        s[2] += __shfl_down_sync(0xffffffffu, s[2], o);
    }
    __shared__ float red[3][8];
    int warp = threadIdx.x >> 5, lane = threadIdx.x & 31;
    if (lane == 0) { red[0][warp] = s[0]; red[1][warp] = s[1]; red[2][warp] = s[2]; }
    __syncthreads();
    if (threadIdx.x == 0) {
        float t0 = 0.f, t1 = 0.f, t2 = 0.f;
#pragma unroll
        for (int w = 0; w < 8; ++w) { t0 += red[0][w]; t1 += red[1][w]; t2 += red[2][w]; }
        atomicAdd(out + 0 * TT, t0 * (1.f / 8192.f));
        atomicAdd(out + 1 * TT, t1 * (1.f / 8192.f));
        atomicAdd(out + 2 * TT, t2 * (1.f / 8192.f));
    }
}

// 4 e4m3 values in a u32 -> 2 cvt + 2 HFMA2 into half2 accumulators
__device__ __forceinline__ void acch(unsigned w, __half2 vv, __half2& a0, __half2& a1) {
    __half2 h0 = __half2(__nv_cvt_fp8x2_to_halfraw2((__nv_fp8x2_storage_t)(w & 0xffffu), __NV_E4M3));
    __half2 h1 = __half2(__nv_cvt_fp8x2_to_halfraw2((__nv_fp8x2_storage_t)(w >> 16), __NV_E4M3));
    a0 = __hfma2(h0, vv, a0);
    a1 = __hfma2(h1, vv, a1);
}

// Grid-wide barrier (all NBLK blocks co-resident by construction).
__device__ __forceinline__ void grid_barrier(unsigned gen) {
    __syncthreads();
    if (threadIdx.x == 0) {
        __threadfence();
        unsigned old = atomicAdd(&g_arrive, 1u);
        if (old == NBLK - 1) {
            g_arrive = 0u;
            __threadfence();
            atomicExch(&g_gen, gen);
        } else {
            unsigned cur;
            do {
                asm volatile("ld.global.acquire.gpu.u32 %0, [%1];" : "=r"(cur) : "l"(&g_gen));
            } while (cur < gen);
        }
    }
    __syncthreads();
}

// ---------------------------------------------------------------------------
// One full RK4 step (4 stages) in a single persistent kernel.
// ---------------------------------------------------------------------------
__global__ void __launch_bounds__(TPB, 4) step_kernel(
    const float* __restrict__ times, int step,
    const float* __restrict__ betas, const float* __restrict__ deltas,
    const float* __restrict__ cs, const float* __restrict__ ps,
    const float* __restrict__ W, const float* __restrict__ bb,
    const float* __restrict__ slope, const float* __restrict__ thr,
    float* __restrict__ out) {

    const float h   = times[step + 1] - times[step];
    const float hd6 = h * (1.f / 6.f);

    const int tid  = threadIdx.x;
    const int c    = blockIdx.x & (CCH - 1);
    const int r    = blockIdx.x / CCH;
    const int col0 = c * COLS_PB;
    const int row0 = r * ROWS_PB;
    const int tsub = tid & 63;       // 64 threads span 1024 cols (16 each)
    const int rg   = tid >> 6;       // 4 row groups
    const int cbase = col0 + tsub * 16;

    __shared__ __half2 sV2[ROWS_PB];
    __shared__ float sred[16 * 128];
    __shared__ int s_last;

    for (int stage = 1; stage <= 4; ++stage) {
        const float ah = (stage == 1) ? 0.f : ((stage == 4) ? h : 0.5f * h);
        const float* kprev = g_k[(stage >= 2) ? (stage - 2) : 0];
        float* kcur = g_k[stage - 1];

        // Stage V values for this block's row window
        if (tid < ROWS_PB) {
            int j = row0 + tid;
            float v = g_state[2 * NN + j];
            if (stage > 1) v = fmaf(ah, kprev[2 * NN + j], v);
            sV2[tid] = __float2half2_rn(v);
        }
        __syncthreads();

        // half2 accumulators: hacc[k] = cols (cbase+2k, +2k+1); 32 adds each.
        __half2 hacc[8];
#pragma unroll
        for (int k = 0; k < 8; ++k) hacc[k] = __float2half2_rn(0.f);

        constexpr size_t RS = (size_t)(4 * NN) / 16;   // uint4 stride for 4 rows
        const uint4* mp = reinterpret_cast<const uint4*>(g_ts8 + (size_t)(row0 + rg) * NN + cbase);

        uint4 q[4];
#pragma unroll
        for (int b = 0; b < 4; ++b) q[b] = mp[(size_t)b * RS];

#pragma unroll
        for (int it = 0; it < ROWS_PB / 16; ++it) {      // 8 outer iters, 4 rows each
            uint4 cur[4];
#pragma unroll
            for (int b = 0; b < 4; ++b) cur[b] = q[b];
            if (it < ROWS_PB / 16 - 1) {
#pragma unroll
                for (int b = 0; b < 4; ++b) q[b] = mp[(size_t)((it + 1) * 4 + b) * RS];
            }
#pragma unroll
            for (int b = 0; b < 4; ++b) {
                __half2 vv = sV2[rg + (it * 4 + b) * 4];
                acch(cur[b].x, vv, hacc[0], hacc[1]);
                acch(cur[b].y, vv, hacc[2], hacc[3]);
                acch(cur[b].z, vv, hacc[4], hacc[5]);
                acch(cur[b].w, vv, hacc[6], hacc[7]);
            }
        }

        float acc[16];
#pragma unroll
        for (int k = 0; k < 8; ++k) {
            float2 f = __half22float2(hacc[k]);
            acc[2 * k]     = f.x;
            acc[2 * k + 1] = f.y;
        }

        // Cross row-group reduction in smem (fixed order)
        if (rg >= 2) {
#pragma unroll
            for (int k = 0; k < 16; ++k) sred[k * 128 + (rg - 2) * 64 + tsub] = acc[k];
        }
        __syncthreads();
        if (rg < 2) {
#pragma unroll
            for (int k = 0; k < 16; ++k) acc[k] += sred[k * 128 + rg * 64 + tsub];
        }
        __syncthreads();
        if (rg == 1) {
#pragma unroll
            for (int k = 0; k < 16; ++k) sred[k * 128 + tsub] = acc[k];
        }
        __syncthreads();
        if (rg == 0) {
#pragma unroll
            for (int k = 0; k < 16; ++k) acc[k] += sred[k * 128 + tsub];
            float4* pp = reinterpret_cast<float4*>(g_partial + (size_t)r * NN + cbase);
            pp[0] = make_float4(acc[0],  acc[1],  acc[2],  acc[3]);
            pp[1] = make_float4(acc[4],  acc[5],  acc[6],  acc[7]);
            pp[2] = make_float4(acc[8],  acc[9],  acc[10], acc[11]);
            pp[3] = make_float4(acc[12], acc[13], acc[14], acc[15]);
        }

        __threadfence();
        __syncthreads();
        if (tid == 0) {
            unsigned old = atomicAdd(&g_cnt[c], 1u);
            s_last = (old == RCH - 1);
        }
        __syncthreads();

        if (s_last) {
            if (tid == 0) { g_cnt[c] = 0u; __threadfence(); }

            // Deterministic ordered reduction over row chunks (4 cols/thread)
            const int i0 = col0 + tid * 4;
            float c0 = 0.f, c1 = 0.f, c2 = 0.f, c3 = 0.f;
#pragma unroll 16
            for (int rr = 0; rr < RCH; ++rr) {
                float4 x = *reinterpret_cast<const float4*>(g_partial + (size_t)rr * NN + i0);
                c0 += x.x; c1 += x.y; c2 += x.z; c3 += x.w;
            }
            float coup[4] = {c0, c1, c2, c3};

            float s0 = 0.f, s1 = 0.f, s2 = 0.f;
#pragma unroll
            for (int k = 0; k < 4; ++k) {
                int i = i0 + k;
                float U = g_state[i], I = g_state[NN + i], V = g_state[2 * NN + i];
                if (stage > 1) {
                    U = fmaf(ah, kprev[i], U);
                    I = fmaf(ah, kprev[NN + i], I);
                    V = fmaf(ah, kprev[2 * NN + i], V);
                }
                float cp  = coup[k] * (1.f / 8192.f) - g_diag[i] * V;
                float inf = fabsf(betas[i]) * U * V;
                float kU  = -inf;
                float kI  = inf - fabsf(deltas[i]) * I;
                float kV  = fabsf(ps[i]) * I - fabsf(cs[i]) * V + cp;
                kcur[i]          = kU;
                kcur[NN + i]     = kI;
                kcur[2 * NN + i] = kV;

                if (stage == 4) {
                    float nU = g_state[i]          + hd6 * (g_k[0][i]          + 2.f * g_k[1][i]          + 2.f * g_k[2][i]          + kU);
                    float nI = g_state[NN + i]     + hd6 * (g_k[0][NN + i]     + 2.f * g_k[1][NN + i]     + 2.f * g_k[2][NN + i]     + kI);
                    float nV = g_state[2 * NN + i] + hd6 * (g_k[0][2 * NN + i] + 2.f * g_k[1][2 * NN + i] + 2.f * g_k[2][2 * NN + i] + kV);
                    g_state[i]          = nU;
                    g_state[NN + i]     = nI;
                    g_state[2 * NN + i] = nV;
#pragma unroll
                    for (int m = 0; m < 3; ++m) {
                        float lin = W[3 * m + 0] * nU + W[3 * m + 1] * nI + W[3 * m + 2] * nV + bb[m];
                        float sg  = sigmoidf_(slope[m] * (lin - thr[m]));
                        if (m == 0) s0 += sg; else if (m == 1) s1 += sg; else s2 += sg;
                    }
                }
            }

            if (stage == 4) {
#pragma unroll
                for (int o = 16; o > 0; o >>= 1) {
                    s0 += __shfl_down_sync(0xffffffffu, s0, o);
                    s1 += __shfl_down_sync(0xffffffffu, s1, o);
                    s2 += __shfl_down_sync(0xffffffffu, s2, o);
                }
                __shared__ float red[3][8];
                int warp = tid >> 5, lane = tid & 31;
                if (lane == 0) { red[0][warp] = s0; red[1][warp] = s1; red[2][warp] = s2; }
                __syncthreads();
                if (tid == 0) {
                    float t0 = 0.f, t1 = 0.f, t2 = 0.f;
#pragma unroll
                    for (int w = 0; w < 8; ++w) { t0 += red[0][w]; t1 += red[1][w]; t2 += red[2][w]; }
                    atomicAdd(out + 0 * TT + step + 1, t0 * (1.f / 8192.f));
                    atomicAdd(out + 1 * TT + step + 1, t1 * (1.f / 8192.f));
                    atomicAdd(out + 2 * TT + step + 1, t2 * (1.f / 8192.f));
                }
            }
        }

        // Stage boundary: grid-wide sync (stage 4 ends at kernel boundary)
        if (stage < 4) grid_barrier((unsigned)(step * 4 + stage));
    }
}

// ---------------------------------------------------------------------------
extern "C" void kernel_launch(void* const* d_in, const int* in_sizes, int n_in,
                              void* d_out, int out_size) {
    const float* times  = (const float*)d_in[0];
    const float* x0     = (const float*)d_in[1];
    const float* betas  = (const float*)d_in[2];
    const float* deltas = (const float*)d_in[3];
    const float* cs     = (const float*)d_in[4];
    const float* ps     = (const float*)d_in[5];
    const float* ts     = (const float*)d_in[6];
    const float* W      = (const float*)d_in[7];
    const float* b      = (const float*)d_in[8];
    const float* slope  = (const float*)d_in[9];
    const float* thr    = (const float*)d_in[10];
    float* out = (float*)d_out;

    convert_kernel<<<(int)(((size_t)NN * NN) / (256 * 16)), 256>>>(ts);
    init_kernel<<<NN / 256, 256>>>(x0, ts, out);
    out0_kernel<<<NN / 256, 256>>>(W, b, slope, thr, out);

    for (int step = 0; step < TT - 1; ++step) {
        step_kernel<<<NBLK, TPB>>>(times, step, betas, deltas, cs, ps, W, b, slope, thr, out);
    }
}

// round 7
// speedup vs baseline: 3.3540x; 1.5115x over previous
#include <cuda_runtime.h>
#include <cuda_fp16.h>
#include <cuda_fp8.h>
#include <cstdint>

#define NN 8192
#define TT 100

constexpr int TPB     = 256;           // threads per block
constexpr int COLS_PB = 1024;          // columns per block (64 threads x 16 cols)
constexpr int CCH     = NN / COLS_PB;  // 8 column chunks
constexpr int ROWS_PB = 128;           // rows per block
constexpr int RCH     = NN / ROWS_PB;  // 64 row chunks
constexpr int NBLK    = CCH * RCH;     // 512 blocks (co-resident: 4/SM x 148 = 592)

// Scratch (device globals: no allocation allowed in kernel_launch)
__device__ __align__(16) unsigned char g_ts8[(size_t)NN * NN]; // ts * N in e4m3 (64 MB)
__device__ float    g_diag[NN];
__device__ float    g_state[3 * NN];                            // U | I | V (SoA)
__device__ float    g_k[4][3 * NN];
__device__ __align__(16) float g_partial[(size_t)RCH * NN];     // 2 MB
__device__ unsigned g_cnt[CCH];                                 // monotone within a replay
__device__ unsigned g_arrive;
__device__ unsigned g_gen;

// ---------------------------------------------------------------------------
__global__ void convert_kernel(const float* __restrict__ ts) {
    size_t base = ((size_t)blockIdx.x * blockDim.x + threadIdx.x) * 16;
    unsigned w[4];
#pragma unroll
    for (int u = 0; u < 4; ++u) {
        float4 f = *reinterpret_cast<const float4*>(ts + base + u * 4);
        __nv_fp8x2_storage_t lo = __nv_cvt_float2_to_fp8x2(
            make_float2(f.x * 8192.f, f.y * 8192.f), __NV_SATFINITE, __NV_E4M3);
        __nv_fp8x2_storage_t hi = __nv_cvt_float2_to_fp8x2(
            make_float2(f.z * 8192.f, f.w * 8192.f), __NV_SATFINITE, __NV_E4M3);
        w[u] = (unsigned)lo | ((unsigned)hi << 16);
    }
    *reinterpret_cast<uint4*>(g_ts8 + base) = make_uint4(w[0], w[1], w[2], w[3]);
}

__global__ void init_kernel(const float* __restrict__ x0,
                            const float* __restrict__ ts,
                            float* __restrict__ out) {
    int i = blockIdx.x * blockDim.x + threadIdx.x;
    if (i < NN) {
        g_state[i]          = fabsf(x0[3 * i + 0]);
        g_state[NN + i]     = fabsf(x0[3 * i + 1]);
        g_state[2 * NN + i] = fabsf(x0[3 * i + 2]);
        float d = ts[(size_t)i * NN + i] * 8192.f;
        __nv_fp8_storage_t s8 = __nv_cvt_float_to_fp8(d, __NV_SATFINITE, __NV_E4M3);
        __half_raw hr = __nv_cvt_fp8_to_halfraw(s8, __NV_E4M3);
        g_diag[i] = __half2float(__half(hr)) * (1.f / 8192.f);
    }
    if (i < 3 * TT) out[i] = 0.f;
    if (i < CCH)    g_cnt[i] = 0u;
    if (i == 0)     { g_arrive = 0u; g_gen = 0u; }   // reset per replay (graph-safe)
}

__device__ __forceinline__ float sigmoidf_(float z) {
    return 1.f / (1.f + expf(-z));
}

__global__ void out0_kernel(const float* __restrict__ W, const float* __restrict__ bb,
                            const float* __restrict__ slope, const float* __restrict__ thr,
                            float* __restrict__ out) {
    int i = blockIdx.x * blockDim.x + threadIdx.x;
    float U = g_state[i], I = g_state[NN + i], V = g_state[2 * NN + i];
    float s[3];
#pragma unroll
    for (int m = 0; m < 3; ++m) {
        float lin = W[3 * m + 0] * U + W[3 * m + 1] * I + W[3 * m + 2] * V + bb[m];
        s[m] = sigmoidf_(slope[m] * (lin - thr[m]));
    }
#pragma unroll
    for (int o = 16; o > 0; o >>= 1) {
        s[0] += __shfl_down_sync(0xffffffffu, s[0], o);
        s[1] += __shfl_down_sync(0xffffffffu, s[1], o);
        s[2] += __shfl_down_sync(0xffffffffu, s[2], o);
    }
    __shared__ float red[3][8];
    int warp = threadIdx.x >> 5, lane = threadIdx.x & 31;
    if (lane == 0) { red[0][warp] = s[0]; red[1][warp] = s[1]; red[2][warp] = s[2]; }
    __syncthreads();
    if (threadIdx.x == 0) {
        float t0 = 0.f, t1 = 0.f, t2 = 0.f;
#pragma unroll
        for (int w = 0; w < 8; ++w) { t0 += red[0][w]; t1 += red[1][w]; t2 += red[2][w]; }
        atomicAdd(out + 0 * TT, t0 * (1.f / 8192.f));
        atomicAdd(out + 1 * TT, t1 * (1.f / 8192.f));
        atomicAdd(out + 2 * TT, t2 * (1.f / 8192.f));
    }
}

// 4 e4m3 values in a u32 -> 2 cvt + 2 HFMA2 into half2 accumulators
__device__ __forceinline__ void acch(unsigned w, __half2 vv, __half2& a0, __half2& a1) {
    __half2 h0 = __half2(__nv_cvt_fp8x2_to_halfraw2((__nv_fp8x2_storage_t)(w & 0xffffu), __NV_E4M3));
    __half2 h1 = __half2(__nv_cvt_fp8x2_to_halfraw2((__nv_fp8x2_storage_t)(w >> 16), __NV_E4M3));
    a0 = __hfma2(h0, vv, a0);
    a1 = __hfma2(h1, vv, a1);
}

// Grid-wide barrier (all NBLK blocks co-resident by construction).
__device__ __forceinline__ void grid_barrier(unsigned gen) {
    __syncthreads();
    if (threadIdx.x == 0) {
        __threadfence();
        unsigned old = atomicAdd(&g_arrive, 1u);
        if (old == NBLK - 1) {
            g_arrive = 0u;
            __threadfence();
            atomicExch(&g_gen, gen);
        } else {
            unsigned cur;
            do {
                asm volatile("ld.global.acquire.gpu.u32 %0, [%1];" : "=r"(cur) : "l"(&g_gen));
            } while (cur < gen);
        }
    }
    __syncthreads();
}

// ---------------------------------------------------------------------------
// One full RK4 step (4 stages). Per stage:
//   Phase A: 512 blocks compute matvec partials (e4m3 -> half2 HFMA2)
//   monotone chunk-counter wait, then Phase B: every block reduces + RHS for
//   its own 16 columns; grid barrier (stages 1-3).
// ---------------------------------------------------------------------------
__global__ void __launch_bounds__(TPB, 4) step_kernel(
    const float* __restrict__ times, int step,
    const float* __restrict__ betas, const float* __restrict__ deltas,
    const float* __restrict__ cs, const float* __restrict__ ps,
    const float* __restrict__ W, const float* __restrict__ bb,
    const float* __restrict__ slope, const float* __restrict__ thr,
    float* __restrict__ out) {

    const float h   = times[step + 1] - times[step];
    const float hd6 = h * (1.f / 6.f);

    const int tid  = threadIdx.x;
    const int c    = blockIdx.x & (CCH - 1);
    const int r    = blockIdx.x / CCH;
    const int col0 = c * COLS_PB;
    const int row0 = r * ROWS_PB;
    const int tsub = tid & 63;       // 64 threads span 1024 cols (16 each)
    const int rg   = tid >> 6;       // 4 row groups
    const int cbase = col0 + tsub * 16;

    // Phase B mapping: 16 cols per block, 16 threads per col, 4 partials each
    const int jl = tid & 15;
    const int g  = tid >> 4;
    const int jcol = blockIdx.x * (NN / NBLK) + jl;
    const int jchunk = jcol >> 10;   // column chunk of jcol

    __shared__ __half2 sV2[ROWS_PB];
    __shared__ float sred[16 * 128];
    __shared__ float sred2[16][17];

    for (int stage = 1; stage <= 4; ++stage) {
        const float ah = (stage == 1) ? 0.f : ((stage == 4) ? h : 0.5f * h);
        const float* kprev = g_k[(stage >= 2) ? (stage - 2) : 0];
        float* kcur = g_k[stage - 1];
        const unsigned tgt = (unsigned)(step * 4 + stage) * (unsigned)RCH;

        // ---- Phase A: matvec partials (R4-verified) ----
        if (tid < ROWS_PB) {
            int j = row0 + tid;
            float v = g_state[2 * NN + j];
            if (stage > 1) v = fmaf(ah, kprev[2 * NN + j], v);
            sV2[tid] = __float2half2_rn(v);
        }
        __syncthreads();

        __half2 hacc[8];
#pragma unroll
        for (int k = 0; k < 8; ++k) hacc[k] = __float2half2_rn(0.f);

        constexpr size_t RS = (size_t)(4 * NN) / 16;   // uint4 stride for 4 rows
        const uint4* mp = reinterpret_cast<const uint4*>(g_ts8 + (size_t)(row0 + rg) * NN + cbase);

        uint4 q[4];
#pragma unroll
        for (int b = 0; b < 4; ++b) q[b] = mp[(size_t)b * RS];

#pragma unroll
        for (int it = 0; it < ROWS_PB / 16; ++it) {      // 8 outer iters, 4 rows each
            uint4 cur[4];
#pragma unroll
            for (int b = 0; b < 4; ++b) cur[b] = q[b];
            if (it < ROWS_PB / 16 - 1) {
#pragma unroll
                for (int b = 0; b < 4; ++b) q[b] = mp[(size_t)((it + 1) * 4 + b) * RS];
            }
#pragma unroll
            for (int b = 0; b < 4; ++b) {
                __half2 vv = sV2[rg + (it * 4 + b) * 4];
                acch(cur[b].x, vv, hacc[0], hacc[1]);
                acch(cur[b].y, vv, hacc[2], hacc[3]);
                acch(cur[b].z, vv, hacc[4], hacc[5]);
                acch(cur[b].w, vv, hacc[6], hacc[7]);
            }
        }

        float acc[16];
#pragma unroll
        for (int k = 0; k < 8; ++k) {
            float2 f = __half22float2(hacc[k]);
            acc[2 * k]     = f.x;
            acc[2 * k + 1] = f.y;
        }

        // Cross row-group reduction in smem (fixed order)
        if (rg >= 2) {
#pragma unroll
            for (int k = 0; k < 16; ++k) sred[k * 128 + (rg - 2) * 64 + tsub] = acc[k];
        }
        __syncthreads();
        if (rg < 2) {
#pragma unroll
            for (int k = 0; k < 16; ++k) acc[k] += sred[k * 128 + rg * 64 + tsub];
        }
        __syncthreads();
        if (rg == 1) {
#pragma unroll
            for (int k = 0; k < 16; ++k) sred[k * 128 + tsub] = acc[k];
        }
        __syncthreads();
        if (rg == 0) {
#pragma unroll
            for (int k = 0; k < 16; ++k) acc[k] += sred[k * 128 + tsub];
            float4* pp = reinterpret_cast<float4*>(g_partial + (size_t)r * NN + cbase);
            pp[0] = make_float4(acc[0],  acc[1],  acc[2],  acc[3]);
            pp[1] = make_float4(acc[4],  acc[5],  acc[6],  acc[7]);
            pp[2] = make_float4(acc[8],  acc[9],  acc[10], acc[11]);
            pp[3] = make_float4(acc[12], acc[13], acc[14], acc[15]);
        }

        __threadfence();
        __syncthreads();
        if (tid == 0) atomicAdd(&g_cnt[c], 1u);

        // ---- wait for all partials of this block's Phase-B chunk ----
        if (tid == 0) {
            unsigned cur;
            do {
                asm volatile("ld.global.acquire.gpu.u32 %0, [%1];" : "=r"(cur) : "l"(&g_cnt[jchunk]));
            } while (cur < tgt);
        }
        __syncthreads();

        // ---- Phase B: reduce partials + RHS for this block's 16 columns ----
        {
            float s = 0.f;
#pragma unroll
            for (int q2 = 0; q2 < 4; ++q2)
                s += g_partial[(size_t)(g * 4 + q2) * NN + jcol];
            sred2[g][jl] = s;
        }
        __syncthreads();

        float s0 = 0.f, s1 = 0.f, s2 = 0.f;
        if (g == 0) {
            float coup = 0.f;
#pragma unroll
            for (int gg = 0; gg < 16; ++gg) coup += sred2[gg][jl];

            int i = jcol;
            float U = g_state[i], I = g_state[NN + i], V = g_state[2 * NN + i];
            if (stage > 1) {
                U = fmaf(ah, kprev[i], U);
                I = fmaf(ah, kprev[NN + i], I);
                V = fmaf(ah, kprev[2 * NN + i], V);
            }
            float cp  = coup * (1.f / 8192.f) - g_diag[i] * V;
            float inf = fabsf(betas[i]) * U * V;
            float kU  = -inf;
            float kI  = inf - fabsf(deltas[i]) * I;
            float kV  = fabsf(ps[i]) * I - fabsf(cs[i]) * V + cp;
            kcur[i]          = kU;
            kcur[NN + i]     = kI;
            kcur[2 * NN + i] = kV;

            if (stage == 4) {
                float nU = g_state[i]          + hd6 * (g_k[0][i]          + 2.f * g_k[1][i]          + 2.f * g_k[2][i]          + kU);
                float nI = g_state[NN + i]     + hd6 * (g_k[0][NN + i]     + 2.f * g_k[1][NN + i]     + 2.f * g_k[2][NN + i]     + kI);
                float nV = g_state[2 * NN + i] + hd6 * (g_k[0][2 * NN + i] + 2.f * g_k[1][2 * NN + i] + 2.f * g_k[2][2 * NN + i] + kV);
                g_state[i]          = nU;
                g_state[NN + i]     = nI;
                g_state[2 * NN + i] = nV;
#pragma unroll
                for (int m = 0; m < 3; ++m) {
                    float lin = W[3 * m + 0] * nU + W[3 * m + 1] * nI + W[3 * m + 2] * nV + bb[m];
                    float sg  = sigmoidf_(slope[m] * (lin - thr[m]));
                    if (m == 0) s0 += sg; else if (m == 1) s1 += sg; else s2 += sg;
                }
            }
        }

        if (stage == 4 && tid < 32) {
#pragma unroll
            for (int o = 8; o > 0; o >>= 1) {
                s0 += __shfl_down_sync(0xffffffffu, s0, o);
                s1 += __shfl_down_sync(0xffffffffu, s1, o);
                s2 += __shfl_down_sync(0xffffffffu, s2, o);
            }
            if (tid == 0) {
                atomicAdd(out + 0 * TT + step + 1, s0 * (1.f / 8192.f));
                atomicAdd(out + 1 * TT + step + 1, s1 * (1.f / 8192.f));
                atomicAdd(out + 2 * TT + step + 1, s2 * (1.f / 8192.f));
            }
        }

        // Stage boundary (stage 4 ends at kernel boundary)
        if (stage < 4) grid_barrier((unsigned)(step * 3 + stage));
    }
}

// ---------------------------------------------------------------------------
extern "C" void kernel_launch(void* const* d_in, const int* in_sizes, int n_in,
                              void* d_out, int out_size) {
    const float* times  = (const float*)d_in[0];
    const float* x0     = (const float*)d_in[1];
    const float* betas  = (const float*)d_in[2];
    const float* deltas = (const float*)d_in[3];
    const float* cs     = (const float*)d_in[4];
    const float* ps     = (const float*)d_in[5];
    const float* ts     = (const float*)d_in[6];
    const float* W      = (const float*)d_in[7];
    const float* b      = (const float*)d_in[8];
    const float* slope  = (const float*)d_in[9];
    const float* thr    = (const float*)d_in[10];
    float* out = (float*)d_out;

    convert_kernel<<<(int)(((size_t)NN * NN) / (256 * 16)), 256>>>(ts);
    init_kernel<<<NN / 256, 256>>>(x0, ts, out);
    out0_kernel<<<NN / 256, 256>>>(W, b, slope, thr, out);

    for (int step = 0; step < TT - 1; ++step) {
        step_kernel<<<NBLK, TPB>>>(times, step, betas, deltas, cs, ps, W, b, slope, thr, out);
    }
}